// round 14
// baseline (speedup 1.0000x reference)
#include <cuda_runtime.h>
#include <stdint.h>

// NaiveVisCache, single kernel: face select + morton3d + int-table gather.
// d_in[0] = norm_ray_origins (B,3) f32, d_in[1] = viewdirs (B,3) f32,
// d_in[2] = cache (128^3,6) int32. Output: B f32 (0.0/1.0).
//
// Semantics (verified rel_err=0.0 across R6-R13): reference lowers v/inf_norm
// as v * fl_rn(1/inf_norm) -> __frcp_rn + __fmul_rn; where-chain falls back to
// face 0 when x*fl(1/x) rounds below 1.0 (~13.9% of rays).
//
// Shape: 8 rays/thread for 8-deep gather MLP, but with PHASED register
// lifetimes (origins die before dirs load) + __launch_bounds__(256,6) reg cap
// so occupancy stays ~75% (R7's monolithic 8-ray hit 48 regs / 53% occ).
// Streams are __ldcs/__stcs (traffic pinned ~167MB, proven R7/R13).

#define MIDPOINT 128

__device__ __forceinline__ unsigned expand_bits(unsigned v) {
    v = (v | (v << 16)) & 0x030000FFu;
    v = (v | (v << 8))  & 0x0300F00Fu;
    v = (v | (v << 4))  & 0x030C30C3u;
    v = (v | (v << 2))  & 0x09249249u;
    return v;
}

__global__ void __launch_bounds__(256, 6)   // cap regs ~42 -> occ >= 75%
vis_cache_kernel(const float4* __restrict__ org4,
                 const float4* __restrict__ dir4,
                 const int*    __restrict__ cache,
                 float4*       __restrict__ out4,
                 int n_oct)  // n_rays / 8
{
    int t = blockIdx.x * blockDim.x + threadIdx.x;
    if (t >= n_oct) return;

    unsigned entry[8];

    // ---- Phase 1: origins -> morton entries. Origin registers die here. ----
    {
        float4 o0 = __ldcs(&org4[6 * t + 0]);
        float4 o1 = __ldcs(&org4[6 * t + 1]);
        float4 o2 = __ldcs(&org4[6 * t + 2]);
        float4 o3 = __ldcs(&org4[6 * t + 3]);
        float4 o4 = __ldcs(&org4[6 * t + 4]);
        float4 o5 = __ldcs(&org4[6 * t + 5]);
        float of[24] = {o0.x,o0.y,o0.z,o0.w, o1.x,o1.y,o1.z,o1.w,
                        o2.x,o2.y,o2.z,o2.w, o3.x,o3.y,o3.z,o3.w,
                        o4.x,o4.y,o4.z,o4.w, o5.x,o5.y,o5.z,o5.w};
        #pragma unroll
        for (int j = 0; j < 8; j++) {
            float cx = fminf(fmaxf((of[3*j+0] * 0.5f + 0.5f) * 128.0f, 0.0f), 127.0f);
            float cy = fminf(fmaxf((of[3*j+1] * 0.5f + 0.5f) * 128.0f, 0.0f), 127.0f);
            float cz = fminf(fmaxf((of[3*j+2] * 0.5f + 0.5f) * 128.0f, 0.0f), 127.0f);
            unsigned idx = expand_bits((unsigned)(int)cx)
                         | (expand_bits((unsigned)(int)cy) << 1)
                         | (expand_bits((unsigned)(int)cz) << 2);
            entry[j] = idx * 6u;
        }
    }

    // ---- Phase 2: dirs -> faces (reciprocal-multiply, bit-exact). ----
    {
        float4 v0 = __ldcs(&dir4[6 * t + 0]);
        float4 v1 = __ldcs(&dir4[6 * t + 1]);
        float4 v2 = __ldcs(&dir4[6 * t + 2]);
        float4 v3 = __ldcs(&dir4[6 * t + 3]);
        float4 v4 = __ldcs(&dir4[6 * t + 4]);
        float4 v5 = __ldcs(&dir4[6 * t + 5]);
        float vf[24] = {v0.x,v0.y,v0.z,v0.w, v1.x,v1.y,v1.z,v1.w,
                        v2.x,v2.y,v2.z,v2.w, v3.x,v3.y,v3.z,v3.w,
                        v4.x,v4.y,v4.z,v4.w, v5.x,v5.y,v5.z,v5.w};
        #pragma unroll
        for (int j = 0; j < 8; j++) {
            float a = vf[3*j+0], b = vf[3*j+1], c = vf[3*j+2];
            float n = fmaxf(fabsf(a), fmaxf(fabsf(b), fabsf(c)));
            float r  = __frcp_rn(n);
            float sa = __fmul_rn(a, r);
            float sb = __fmul_rn(b, r);
            float sc = __fmul_rn(c, r);

            int face = 0;
            if (sa >=  1.0f) face = 0;
            if (sa <= -1.0f) face = 1;
            if (sb >=  1.0f) face = 2;
            if (sb <= -1.0f) face = 3;
            if (sc >=  1.0f) face = 4;
            if (sc <= -1.0f) face = 5;

            entry[j] += (unsigned)face;
        }
    }

    // ---- Phase 3: 8 independent gathers in flight (default policy). ----
    int val[8];
    #pragma unroll
    for (int j = 0; j < 8; j++) val[j] = __ldg(&cache[entry[j]]);

    __stcs(&out4[2 * t + 0], make_float4(val[0] > MIDPOINT ? 1.0f : 0.0f,
                                         val[1] > MIDPOINT ? 1.0f : 0.0f,
                                         val[2] > MIDPOINT ? 1.0f : 0.0f,
                                         val[3] > MIDPOINT ? 1.0f : 0.0f));
    __stcs(&out4[2 * t + 1], make_float4(val[4] > MIDPOINT ? 1.0f : 0.0f,
                                         val[5] > MIDPOINT ? 1.0f : 0.0f,
                                         val[6] > MIDPOINT ? 1.0f : 0.0f,
                                         val[7] > MIDPOINT ? 1.0f : 0.0f));
}

extern "C" void kernel_launch(void* const* d_in, const int* in_sizes, int n_in,
                              void* d_out, int out_size)
{
    const float4* org4  = (const float4*)d_in[0];
    const float4* dir4  = (const float4*)d_in[1];
    const int*    cache = (const int*)d_in[2];
    float4*       out4  = (float4*)d_out;

    int n_rays = in_sizes[0] / 3;   // 4194304
    int n_oct  = n_rays / 8;        // 524288

    vis_cache_kernel<<<(n_oct + 255) / 256, 256>>>(org4, dir4, cache, out4, n_oct);
}

// round 15
// speedup vs baseline: 1.2326x; 1.2326x over previous
#include <cuda_runtime.h>
#include <stdint.h>

// NaiveVisCache, single kernel: face select + morton3d + int-table gather.
// d_in[0] = norm_ray_origins (B,3) f32, d_in[1] = viewdirs (B,3) f32,
// d_in[2] = cache (128^3,6) int32. Output: B f32 (0.0/1.0).
//
// Semantics (verified rel_err=0.0 across R6-R14): reference lowers v/inf_norm
// as v * fl_rn(1/inf_norm) -> __frcp_rn + __fmul_rn; where-chain falls back to
// face 0 when x*fl(1/x) rounds below 1.0.
//
// R15 change vs R13 (37.2us): stream loads were lane-strided 48B -> each
// LDG.128 touched 12 lines (3x the wavefronts, 3x completion latency per the
// L1tex queue model lat = Q + nL). Now each warp loads its 96 contiguous
// float4 COALESCED (nL=4), stages in a private smem tile, and re-reads
// per-quad via LDS. Gather/hints/math identical to R13.

#define MIDPOINT 128

__device__ __forceinline__ unsigned expand_bits(unsigned v) {
    v = (v | (v << 16)) & 0x030000FFu;
    v = (v | (v << 8))  & 0x0300F00Fu;
    v = (v | (v << 4))  & 0x030C30C3u;
    v = (v | (v << 2))  & 0x09249249u;
    return v;
}

__global__ void __launch_bounds__(256)
vis_cache_kernel(const float4* __restrict__ org4,
                 const float4* __restrict__ dir4,
                 const int*    __restrict__ cache,
                 float4*       __restrict__ out4,
                 int n_quads)  // n_rays / 4; grid sized so every warp is full
{
    __shared__ float4 stage[8][96];   // per-warp private tile: 32 quads * 3 float4

    int warp = threadIdx.x >> 5;
    int lane = threadIdx.x & 31;
    int warpQuadBase = (blockIdx.x * 8 + warp) * 32;
    int t = warpQuadBase + lane;      // this thread's quad
    if (warpQuadBase >= n_quads) return;   // whole-warp exit; n_quads % 32 == 0

    // ---- Stage origins: coalesced (nL=4 per LDG.128), then per-quad reload ----
    {
        const float4* g = org4 + (size_t)warpQuadBase * 3;
        float4 r0 = __ldcs(&g[lane]);
        float4 r1 = __ldcs(&g[lane + 32]);
        float4 r2 = __ldcs(&g[lane + 64]);
        stage[warp][lane]      = r0;
        stage[warp][lane + 32] = r1;
        stage[warp][lane + 64] = r2;
    }
    __syncwarp();
    float4 oa = stage[warp][3 * lane + 0];
    float4 ob = stage[warp][3 * lane + 1];
    float4 oc = stage[warp][3 * lane + 2];
    __syncwarp();

    // ---- Stage viewdirs the same way (reuse the tile) ----
    {
        const float4* g = dir4 + (size_t)warpQuadBase * 3;
        float4 r0 = __ldcs(&g[lane]);
        float4 r1 = __ldcs(&g[lane + 32]);
        float4 r2 = __ldcs(&g[lane + 64]);
        stage[warp][lane]      = r0;
        stage[warp][lane + 32] = r1;
        stage[warp][lane + 64] = r2;
    }
    __syncwarp();
    float4 va = stage[warp][3 * lane + 0];
    float4 vb = stage[warp][3 * lane + 1];
    float4 vc = stage[warp][3 * lane + 2];

    float of[12] = {oa.x, oa.y, oa.z, oa.w, ob.x, ob.y, ob.z, ob.w, oc.x, oc.y, oc.z, oc.w};
    float vf[12] = {va.x, va.y, va.z, va.w, vb.x, vb.y, vb.z, vb.w, vc.x, vc.y, vc.z, vc.w};

    // Phase 1: morton base indices (exact-integer path).
    unsigned entry[4];
    #pragma unroll
    for (int j = 0; j < 4; j++) {
        float cx = fminf(fmaxf((of[3 * j + 0] * 0.5f + 0.5f) * 128.0f, 0.0f), 127.0f);
        float cy = fminf(fmaxf((of[3 * j + 1] * 0.5f + 0.5f) * 128.0f, 0.0f), 127.0f);
        float cz = fminf(fmaxf((of[3 * j + 2] * 0.5f + 0.5f) * 128.0f, 0.0f), 127.0f);

        unsigned idx = expand_bits((unsigned)(int)cx)
                     | (expand_bits((unsigned)(int)cy) << 1)
                     | (expand_bits((unsigned)(int)cz) << 2);
        entry[j] = idx * 6u;
    }

    // Phase 2: face select (reciprocal-multiply, bit-matching the reference).
    #pragma unroll
    for (int j = 0; j < 4; j++) {
        float a = vf[3 * j + 0];
        float b = vf[3 * j + 1];
        float c = vf[3 * j + 2];

        float n = fmaxf(fabsf(a), fmaxf(fabsf(b), fabsf(c)));
        float r  = __frcp_rn(n);
        float sa = __fmul_rn(a, r);
        float sb = __fmul_rn(b, r);
        float sc = __fmul_rn(c, r);

        int face = 0;
        if (sa >=  1.0f) face = 0;
        if (sa <= -1.0f) face = 1;
        if (sb >=  1.0f) face = 2;
        if (sb <= -1.0f) face = 3;
        if (sc >=  1.0f) face = 4;
        if (sc <= -1.0f) face = 5;

        entry[j] += (unsigned)face;
    }

    // Phase 3: 4 independent gathers in flight (default policy: table owns L2).
    int v0 = __ldg(&cache[entry[0]]);
    int v1 = __ldg(&cache[entry[1]]);
    int v2 = __ldg(&cache[entry[2]]);
    int v3 = __ldg(&cache[entry[3]]);

    float4 res = make_float4(v0 > MIDPOINT ? 1.0f : 0.0f,
                             v1 > MIDPOINT ? 1.0f : 0.0f,
                             v2 > MIDPOINT ? 1.0f : 0.0f,
                             v3 > MIDPOINT ? 1.0f : 0.0f);

    __stcs(&out4[t], res);   // coalesced, never re-read
}

extern "C" void kernel_launch(void* const* d_in, const int* in_sizes, int n_in,
                              void* d_out, int out_size)
{
    const float4* org4  = (const float4*)d_in[0];
    const float4* dir4  = (const float4*)d_in[1];
    const int*    cache = (const int*)d_in[2];
    float4*       out4  = (float4*)d_out;

    int n_rays  = in_sizes[0] / 3;   // 4194304
    int n_quads = n_rays / 4;        // 1048576 (divisible by 32)

    vis_cache_kernel<<<(n_quads + 255) / 256, 256>>>(org4, dir4, cache, out4, n_quads);
}